// round 1
// baseline (speedup 1.0000x reference)
#include <cuda_runtime.h>
#include <cuda_bf16.h>
#include <cstdint>

#define NPOINTS 300000
#define NPAIRS  100000
#define KOFF    27
#define CIN     32
#define COUT    64
#define GROUPS  8
#define EPS     1e-5f
#define SLOPE   0.01f

// scratch: per-group sum (8) + sumsq (8), plus index-dtype mode flag
__device__ float g_stats[16];
__device__ int   g_idx_mode;   // 0 = int64 indices, 1 = int32 indices

__global__ void zero_stats() {
    int t = threadIdx.x;
    if (t < 16) g_stats[t] = 0.0f;
    if (t == 16) g_idx_mode = 0;
}

// Detect whether index arrays are int64 (as declared) or int32 (jax x64 off).
// If int32 data is read as int64, high words are random indices -> values >= 2^32.
__global__ void detect_mode(const long long* __restrict__ a,
                            const long long* __restrict__ b, int n) {
    int t = threadIdx.x;
    int lim = n < 4096 ? n : 4096;
    int bad = 0;
    for (int i = t; i < lim; i += blockDim.x) {
        long long v = a[i], w = b[i];
        if (v < 0 || v >= NPOINTS || w < 0 || w >= NPOINTS) bad = 1;
    }
    if (bad) g_idx_mode = 1;
}

__device__ __forceinline__ long long fetch_idx(const void* base, long long pos, int mode) {
    if (mode) return (long long)((const int*)base)[pos];
    return ((const long long*)base)[pos];
}

// ---------------------------------------------------------------------------
// Conv + scatter-add.
// grid = (ceil(NPAIRS/256), KOFF), block = 256.
// 8 lanes cooperate on one pair: coalesced 128B feature-row load, feature
// broadcast via shfl(width=8); each lane owns 8 output channels, accumulated
// as 4 packed f32x2 registers; scatter via red.global.add.v4.f32.
// ---------------------------------------------------------------------------
#define GI 8   // pairs per 8-lane group

__global__ void __launch_bounds__(256)
conv_scatter(const float* __restrict__ feats,
             const float* __restrict__ weight,
             const void*  __restrict__ in_idx,
             const void*  __restrict__ out_idx,
             float* __restrict__ out)
{
    __shared__ float sW[CIN * COUT];           // 8 KB, W[k]
    const int k   = blockIdx.y;
    const int tid = threadIdx.x;

    // stage W[k] into smem (vectorized)
    {
        const float4* src = (const float4*)(weight + (size_t)k * CIN * COUT);
        float4* dst = (float4*)sW;
        #pragma unroll
        for (int i = tid; i < CIN * COUT / 4; i += 256) dst[i] = src[i];
    }
    __syncthreads();

    const int mode = g_idx_mode;
    const int lane = tid & 31;
    const int s    = lane & 7;                 // lane-in-group: owns channels [8s, 8s+8)
    const int gidb = tid >> 3;                 // group index in block: 0..31
    const long long kbase = (long long)k * NPAIRS;
    const unsigned long long* sW2 = (const unsigned long long*)sW;

    const int p0 = (blockIdx.x * 32 + gidb) * GI;

    for (int it = 0; it < GI; ++it) {
        const int p = p0 + it;
        const bool valid = (p < NPAIRS);

        long long i = 0, o = 0;
        float4 f4 = make_float4(0.f, 0.f, 0.f, 0.f);
        if (valid) {
            i = fetch_idx(in_idx,  kbase + p, mode);
            o = fetch_idx(out_idx, kbase + p, mode);
            f4 = ((const float4*)feats)[i * 8 + s];   // coalesced: 8 lanes cover the 128B row
        }
        float vals[4] = {f4.x, f4.y, f4.z, f4.w};

        unsigned long long A0 = 0ull, A1 = 0ull, A2 = 0ull, A3 = 0ull;

        #pragma unroll
        for (int c4 = 0; c4 < 8; ++c4) {
            #pragma unroll
            for (int comp = 0; comp < 4; ++comp) {
                const int c = c4 * 4 + comp;
                float f = __shfl_sync(0xffffffffu, vals[comp], c4, 8);
                unsigned int fb = __float_as_uint(f);
                unsigned long long ff;
                asm("mov.b64 %0, {%1, %2};" : "=l"(ff) : "r"(fb), "r"(fb));
                const unsigned long long* wp = sW2 + (size_t)c * 32 + s * 4;
                unsigned long long w0 = wp[0], w1 = wp[1], w2 = wp[2], w3 = wp[3];
                asm("fma.rn.f32x2 %0, %1, %2, %0;" : "+l"(A0) : "l"(ff), "l"(w0));
                asm("fma.rn.f32x2 %0, %1, %2, %0;" : "+l"(A1) : "l"(ff), "l"(w1));
                asm("fma.rn.f32x2 %0, %1, %2, %0;" : "+l"(A2) : "l"(ff), "l"(w2));
                asm("fma.rn.f32x2 %0, %1, %2, %0;" : "+l"(A3) : "l"(ff), "l"(w3));
            }
        }

        if (valid) {
            unsigned int a0l, a0h, a1l, a1h, a2l, a2h, a3l, a3h;
            asm("mov.b64 {%0, %1}, %2;" : "=r"(a0l), "=r"(a0h) : "l"(A0));
            asm("mov.b64 {%0, %1}, %2;" : "=r"(a1l), "=r"(a1h) : "l"(A1));
            asm("mov.b64 {%0, %1}, %2;" : "=r"(a2l), "=r"(a2h) : "l"(A2));
            asm("mov.b64 {%0, %1}, %2;" : "=r"(a3l), "=r"(a3h) : "l"(A3));
            float* dst = out + (size_t)o * COUT + s * 8;
            asm volatile("red.global.add.v4.f32 [%0], {%1, %2, %3, %4};"
                         :: "l"(dst),
                            "f"(__uint_as_float(a0l)), "f"(__uint_as_float(a0h)),
                            "f"(__uint_as_float(a1l)), "f"(__uint_as_float(a1h))
                         : "memory");
            asm volatile("red.global.add.v4.f32 [%0], {%1, %2, %3, %4};"
                         :: "l"(dst + 4),
                            "f"(__uint_as_float(a2l)), "f"(__uint_as_float(a2h)),
                            "f"(__uint_as_float(a3l)), "f"(__uint_as_float(a3h))
                         : "memory");
        }
    }
}

// ---------------------------------------------------------------------------
// GroupNorm reduction: per-group sum & sumsq over all N points x 8 channels.
// block = 256 (4 rows x 64 channels), grid-stride over rows.
// ---------------------------------------------------------------------------
__global__ void __launch_bounds__(256)
gn_reduce(const float* __restrict__ out)
{
    const int tid = threadIdx.x;
    const int c   = tid & 63;
    const int rb  = tid >> 6;              // 0..3
    float s = 0.f, s2 = 0.f;
    for (long long r = (long long)blockIdx.x * 4 + rb; r < NPOINTS;
         r += (long long)gridDim.x * 4) {
        float x = out[r * COUT + c];
        s  += x;
        s2 += x * x;
    }
    __shared__ float sh[512];
    sh[tid] = s;
    sh[256 + tid] = s2;
    __syncthreads();
    if (tid < 16) {
        const int g  = tid & 7;
        const int sq = (tid >> 3) * 256;
        float acc = 0.f;
        #pragma unroll
        for (int r = 0; r < 4; ++r)
            #pragma unroll
            for (int cc = 0; cc < 8; ++cc)
                acc += sh[sq + r * 64 + g * 8 + cc];
        atomicAdd(&g_stats[(tid >> 3) * 8 + g], acc);
    }
}

// ---------------------------------------------------------------------------
// Normalize + affine + LeakyReLU, in place over d_out. One float4 per thread.
// ---------------------------------------------------------------------------
__global__ void __launch_bounds__(256)
gn_final(float* __restrict__ out,
         const float* __restrict__ gamma,
         const float* __restrict__ beta)
{
    const long long i4 = (long long)blockIdx.x * blockDim.x + threadIdx.x;
    if (i4 >= (long long)NPOINTS * (COUT / 4)) return;
    const int c4 = (int)(i4 & 15);         // float4 index within row
    const int g  = c4 >> 1;                // group (8 channels = 2 float4s)
    const float inv = 1.0f / ((float)NPOINTS * (COUT / GROUPS));
    const float mean = g_stats[g] * inv;
    const float var  = g_stats[8 + g] * inv - mean * mean;
    const float rs   = rsqrtf(var + EPS);

    float4 x  = ((const float4*)out)[i4];
    float4 ga = ((const float4*)gamma)[c4];
    float4 be = ((const float4*)beta)[c4];

    float v;
    v = (x.x - mean) * rs * ga.x + be.x;  x.x = v >= 0.f ? v : SLOPE * v;
    v = (x.y - mean) * rs * ga.y + be.y;  x.y = v >= 0.f ? v : SLOPE * v;
    v = (x.z - mean) * rs * ga.z + be.z;  x.z = v >= 0.f ? v : SLOPE * v;
    v = (x.w - mean) * rs * ga.w + be.w;  x.w = v >= 0.f ? v : SLOPE * v;

    ((float4*)out)[i4] = x;
}

extern "C" void kernel_launch(void* const* d_in, const int* in_sizes, int n_in,
                              void* d_out, int out_size)
{
    const float* feats  = (const float*)d_in[0];
    const float* weight = (const float*)d_in[1];
    const float* gamma  = (const float*)d_in[2];
    const float* beta   = (const float*)d_in[3];
    const void*  in_idx  = d_in[4];
    const void*  out_idx = d_in[5];
    float* out = (float*)d_out;

    cudaMemsetAsync(d_out, 0, (size_t)out_size * sizeof(float));
    zero_stats<<<1, 32>>>();
    detect_mode<<<1, 256>>>((const long long*)in_idx, (const long long*)out_idx,
                            in_sizes[4]);

    dim3 cgrid((NPAIRS + 255) / 256, KOFF);
    conv_scatter<<<cgrid, 256>>>(feats, weight, in_idx, out_idx, out);

    gn_reduce<<<2048, 256>>>(out);

    const long long n4 = (long long)NPOINTS * (COUT / 4);
    gn_final<<<(unsigned)((n4 + 255) / 256), 256>>>(out, gamma, beta);
}

// round 3
// speedup vs baseline: 2.9156x; 2.9156x over previous
#include <cuda_runtime.h>
#include <cuda_bf16.h>
#include <cstdint>

#define NPOINTS 300000
#define NPAIRS  100000
#define KOFF    27
#define CIN     32
#define COUT    64
#define GROUPS  8
#define EPS     1e-5f
#define SLOPE   0.01f

// scratch: per-group sum (8) + sumsq (8), plus index-dtype mode flag
__device__ float g_stats[16];
__device__ int   g_idx_mode;   // 0 = int64 indices, 1 = int32 indices

__global__ void zero_stats() {
    int t = threadIdx.x;
    if (t < 16) g_stats[t] = 0.0f;
    if (t == 16) g_idx_mode = 0;
}

// Detect whether index arrays are int64 (as declared) or int32 (jax x64 off).
__global__ void detect_mode(const long long* __restrict__ a,
                            const long long* __restrict__ b, int n) {
    int t = threadIdx.x;
    int lim = n < 4096 ? n : 4096;
    int bad = 0;
    for (int i = t; i < lim; i += blockDim.x) {
        long long v = a[i], w = b[i];
        if (v < 0 || v >= NPOINTS || w < 0 || w >= NPOINTS) bad = 1;
    }
    if (bad) g_idx_mode = 1;
}

__device__ __forceinline__ long long fetch_idx(const void* base, long long pos, int mode) {
    if (mode) return (long long)((const int*)base)[pos];
    return ((const long long*)base)[pos];
}

// ---------------------------------------------------------------------------
// Conv as register-tiled GEMM + scatter.
// grid = (ceil(NPAIRS/256), KOFF), block = 256 (8 warps).
// Block tile: 256 pairs x 64 channels. Thread tile: 8 pairs x 8 channels.
// Warp cc owns channels [8*cc, 8*cc+8); lane pc owns pairs
// {pc*2 + j*64 + r : j=0..3, r=0..1} (float2-interleaved, conflict-free LDS).
// A staged transposed in smem [i][p]; W[k] staged once; FFMA2 throughout.
// ---------------------------------------------------------------------------
__global__ void __launch_bounds__(256, 2)
conv_gemm(const float* __restrict__ feats,
          const float* __restrict__ weight,
          const void*  __restrict__ in_idx,
          const void*  __restrict__ out_idx,
          float* __restrict__ out)
{
    __shared__ float A_s[32 * 256];   // 32 KB: A_s[i][p] = feats[in_p][i]
    __shared__ float W_s[CIN * COUT]; // 8 KB
    __shared__ int   o_s[256];

    const int k   = blockIdx.y;
    const int tid = threadIdx.x;
    const int mode = g_idx_mode;

    // stage W[k]
    {
        const float4* src = (const float4*)(weight + (size_t)k * CIN * COUT);
        float4* dst = (float4*)W_s;
        dst[tid]       = src[tid];
        dst[tid + 256] = src[tid + 256];
    }

    // indices + gather own pair's feature row into transposed A tile
    const int p = blockIdx.x * 256 + tid;
    const bool valid = (p < NPAIRS);
    const long long kb = (long long)k * NPAIRS;
    if (valid) {
        long long ii = fetch_idx(in_idx,  kb + p, mode);
        o_s[tid] = (int)fetch_idx(out_idx, kb + p, mode);
        const float4* fr = (const float4*)(feats + ii * CIN);
        #pragma unroll
        for (int j = 0; j < 8; ++j) {
            float4 v = fr[j];
            A_s[(4 * j + 0) * 256 + tid] = v.x;
            A_s[(4 * j + 1) * 256 + tid] = v.y;
            A_s[(4 * j + 2) * 256 + tid] = v.z;
            A_s[(4 * j + 3) * 256 + tid] = v.w;
        }
    } else {
        o_s[tid] = -1;
        #pragma unroll
        for (int j = 0; j < 32; ++j) A_s[j * 256 + tid] = 0.0f;
    }
    __syncthreads();

    const int cc = tid >> 5;   // warp id: channels cc*8 .. cc*8+7
    const int pc = tid & 31;

    unsigned long long acc[8][4];
    #pragma unroll
    for (int j = 0; j < 8; ++j)
        #pragma unroll
        for (int q = 0; q < 4; ++q) acc[j][q] = 0ull;

    const float2*     A2 = (const float2*)A_s;          // 128 float2 per i-row
    const ulonglong2* W2 = (const ulonglong2*)W_s;      // 16 ull2 per i-row

    #pragma unroll
    for (int i = 0; i < CIN; ++i) {
        float2 a0 = A2[i * 128 + pc];        // pairs pc*2, pc*2+1
        float2 a1 = A2[i * 128 + pc + 32];   // +64
        float2 a2 = A2[i * 128 + pc + 64];   // +128
        float2 a3 = A2[i * 128 + pc + 96];   // +192
        ulonglong2 b0 = W2[i * 16 + cc * 2];       // channels cc*8 .. +3
        ulonglong2 b1 = W2[i * 16 + cc * 2 + 1];   // channels cc*8+4 .. +7
        float av[8] = {a0.x, a0.y, a1.x, a1.y, a2.x, a2.y, a3.x, a3.y};
        #pragma unroll
        for (int j = 0; j < 8; ++j) {
            unsigned int fb = __float_as_uint(av[j]);
            unsigned long long ff;
            asm("mov.b64 %0, {%1, %2};" : "=l"(ff) : "r"(fb), "r"(fb));
            asm("fma.rn.f32x2 %0, %1, %2, %0;" : "+l"(acc[j][0]) : "l"(ff), "l"(b0.x));
            asm("fma.rn.f32x2 %0, %1, %2, %0;" : "+l"(acc[j][1]) : "l"(ff), "l"(b0.y));
            asm("fma.rn.f32x2 %0, %1, %2, %0;" : "+l"(acc[j][2]) : "l"(ff), "l"(b1.x));
            asm("fma.rn.f32x2 %0, %1, %2, %0;" : "+l"(acc[j][3]) : "l"(ff), "l"(b1.y));
        }
    }

    // scatter-add: 2 x red.global.add.v4 per pair
    #pragma unroll
    for (int j = 0; j < 8; ++j) {
        const int pl = pc * 2 + (j >> 1) * 64 + (j & 1);
        const int o  = o_s[pl];
        if (o >= 0) {
            unsigned int r0l, r0h, r1l, r1h, r2l, r2h, r3l, r3h;
            asm("mov.b64 {%0, %1}, %2;" : "=r"(r0l), "=r"(r0h) : "l"(acc[j][0]));
            asm("mov.b64 {%0, %1}, %2;" : "=r"(r1l), "=r"(r1h) : "l"(acc[j][1]));
            asm("mov.b64 {%0, %1}, %2;" : "=r"(r2l), "=r"(r2h) : "l"(acc[j][2]));
            asm("mov.b64 {%0, %1}, %2;" : "=r"(r3l), "=r"(r3h) : "l"(acc[j][3]));
            float* dst = out + (size_t)o * COUT + cc * 8;
            asm volatile("red.global.add.v4.f32 [%0], {%1, %2, %3, %4};"
                         :: "l"(dst),
                            "f"(__uint_as_float(r0l)), "f"(__uint_as_float(r0h)),
                            "f"(__uint_as_float(r1l)), "f"(__uint_as_float(r1h))
                         : "memory");
            asm volatile("red.global.add.v4.f32 [%0], {%1, %2, %3, %4};"
                         :: "l"(dst + 4),
                            "f"(__uint_as_float(r2l)), "f"(__uint_as_float(r2h)),
                            "f"(__uint_as_float(r3l)), "f"(__uint_as_float(r3h))
                         : "memory");
        }
    }
}

// ---------------------------------------------------------------------------
// GroupNorm reduction: float4-vectorized, per-group sums via shared atomics.
// ---------------------------------------------------------------------------
__global__ void __launch_bounds__(256)
gn_reduce(const float* __restrict__ out)
{
    const int tid = threadIdx.x;
    const int c4  = tid & 15;          // float4 index within a 64-ch row
    const int rb  = tid >> 4;          // 0..15 rows per block-iter
    float s = 0.f, s2 = 0.f;
    for (long long r = (long long)blockIdx.x * 16 + rb; r < NPOINTS;
         r += (long long)gridDim.x * 16) {
        float4 x = ((const float4*)out)[r * 16 + c4];
        s  += x.x + x.y + x.z + x.w;
        s2 += x.x * x.x + x.y * x.y + x.z * x.z + x.w * x.w;
    }
    __shared__ float sg[8], s2g[8];
    if (tid < 8) { sg[tid] = 0.f; s2g[tid] = 0.f; }
    __syncthreads();
    const int g = c4 >> 1;
    atomicAdd(&sg[g], s);
    atomicAdd(&s2g[g], s2);
    __syncthreads();
    if (tid < 8) {
        atomicAdd(&g_stats[tid],     sg[tid]);
        atomicAdd(&g_stats[8 + tid], s2g[tid]);
    }
}

// ---------------------------------------------------------------------------
// Normalize + affine + LeakyReLU, in place. One float4 per thread.
// ---------------------------------------------------------------------------
__global__ void __launch_bounds__(256)
gn_final(float* __restrict__ out,
         const float* __restrict__ gamma,
         const float* __restrict__ beta)
{
    const long long i4 = (long long)blockIdx.x * blockDim.x + threadIdx.x;
    if (i4 >= (long long)NPOINTS * (COUT / 4)) return;
    const int c4 = (int)(i4 & 15);
    const int g  = c4 >> 1;
    const float inv = 1.0f / ((float)NPOINTS * (COUT / GROUPS));
    const float mean = g_stats[g] * inv;
    const float var  = g_stats[8 + g] * inv - mean * mean;
    const float rs   = rsqrtf(var + EPS);

    float4 x  = ((const float4*)out)[i4];
    float4 ga = ((const float4*)gamma)[c4];
    float4 be = ((const float4*)beta)[c4];

    float v;
    v = (x.x - mean) * rs * ga.x + be.x;  x.x = v >= 0.f ? v : SLOPE * v;
    v = (x.y - mean) * rs * ga.y + be.y;  x.y = v >= 0.f ? v : SLOPE * v;
    v = (x.z - mean) * rs * ga.z + be.z;  x.z = v >= 0.f ? v : SLOPE * v;
    v = (x.w - mean) * rs * ga.w + be.w;  x.w = v >= 0.f ? v : SLOPE * v;

    ((float4*)out)[i4] = x;
}

extern "C" void kernel_launch(void* const* d_in, const int* in_sizes, int n_in,
                              void* d_out, int out_size)
{
    const float* feats  = (const float*)d_in[0];
    const float* weight = (const float*)d_in[1];
    const float* gamma  = (const float*)d_in[2];
    const float* beta   = (const float*)d_in[3];
    const void*  in_idx  = d_in[4];
    const void*  out_idx = d_in[5];
    float* out = (float*)d_out;

    cudaMemsetAsync(d_out, 0, (size_t)out_size * sizeof(float));
    zero_stats<<<1, 32>>>();
    detect_mode<<<1, 256>>>((const long long*)in_idx, (const long long*)out_idx,
                            in_sizes[4]);

    dim3 cgrid((NPAIRS + 255) / 256, KOFF);
    conv_gemm<<<cgrid, 256>>>(feats, weight, in_idx, out_idx, out);

    gn_reduce<<<1024, 256>>>(out);

    const long long n4 = (long long)NPOINTS * (COUT / 4);
    gn_final<<<(unsigned)((n4 + 255) / 256), 256>>>(out, gamma, beta);
}